// round 17
// baseline (speedup 1.0000x reference)
#include <cuda_runtime.h>
#include <cuda_fp16.h>
#include <math.h>
#include <stdint.h>

#define NB 8
#define NT 2048
#define NC 1024
#define NH 128
#define NBT (NB*NT)

// fp16 scratch
__device__ __half g_Wf[3*NH*NC];   // Wq|Wk|Wv fp16 (from split_w)
__device__ __half g_Qf[NBT*NH];    // Q * scale, [b][t][d]
__device__ __half g_Kf[NBT*NH];    // [b][t][d]
__device__ __half g_Vtf[NB*NH*NT]; // V transposed: [b][d][t]

// ===========================================================================
// Helpers (generic sm_80+ PTX)
// ===========================================================================
__device__ __forceinline__ void mma_f16(float* d, const uint32_t* a, const uint32_t* b) {
    asm volatile(
        "mma.sync.aligned.m16n8k16.row.col.f32.f16.f16.f32 "
        "{%0,%1,%2,%3}, {%4,%5,%6,%7}, {%8,%9}, {%0,%1,%2,%3};"
        : "+f"(d[0]), "+f"(d[1]), "+f"(d[2]), "+f"(d[3])
        : "r"(a[0]), "r"(a[1]), "r"(a[2]), "r"(a[3]), "r"(b[0]), "r"(b[1]));
}
__device__ __forceinline__ void ldm_x4(uint32_t* r, uint32_t a) {
    asm volatile("ldmatrix.sync.aligned.m8n8.x4.shared.b16 {%0,%1,%2,%3}, [%4];"
        : "=r"(r[0]), "=r"(r[1]), "=r"(r[2]), "=r"(r[3]) : "r"(a));
}
__device__ __forceinline__ uint32_t pack_h2(float x, float y) {
    __half2 h = __floats2half2_rn(x, y);
    return *(uint32_t*)&h;
}
__device__ __forceinline__ uint32_t smem_u32(const void* p) {
    uint32_t a;
    asm("{ .reg .u64 t; cvta.to.shared.u64 t, %1; cvt.u32.u64 %0, t; }" : "=r"(a) : "l"(p));
    return a;
}
#define CPA16(dst, src) \
    asm volatile("cp.async.cg.shared.global [%0], [%1], 16;" :: "r"(dst), "l"(src))
#define CP_COMMIT asm volatile("cp.async.commit_group;" ::: "memory")
#define CP_WAIT(n) asm volatile("cp.async.wait_group %0;" :: "n"(n) : "memory")

// ===========================================================================
// Pre-pass: convert W only to fp16 (~1.5MB, ~3us). x converts inside qkv.
// ===========================================================================
#define WBLK (NH * NC / 4 / 256)       // 128 per W

__global__ __launch_bounds__(256, 8)
void split_w(const float* __restrict__ Wq,
             const float* __restrict__ Wk,
             const float* __restrict__ Wv) {
    const int j = (int)blockIdx.x;
    const int widx = j / WBLK;
    const float* W = (widx == 0) ? Wq : (widx == 1) ? Wk : Wv;
    size_t i = (size_t)(j % WBLK) * 256 + threadIdx.x;
    float4 v = ((const float4*)W)[i];
    size_t o = (size_t)widx * (NH * NC / 4) + i;
    ((uint2*)g_Wf)[o] = make_uint2(pack_h2(v.x, v.y), pack_h2(v.z, v.w));
}

// ===========================================================================
// QKV projection, fp16 GEMM (m16n8k16).
// A: fp32 x -> LDG register prefetch (2 chunks ahead) -> cvt -> STS fp16.
// B: cp.async from pre-split g_Wf (2 chunks ahead).
// Stage layout: [A plane 10240B][B plane 10240B] x 2 stages.
// ===========================================================================
#define PLANE4 10240                  // 128 rows * 80B
#define STAGEB (2 * PLANE4)           // 20480
#define QKV_SMEM (2 * STAGEB)         // 40960

__device__ __forceinline__ void qkv_load_B(uint32_t sb, int st, int widx,
                                           int k0, int tid) {
    #pragma unroll
    for (int i = 0; i < 2; i++) {
        int c = tid + i * 256;             // 512 chunks of 16B
        int row = c >> 2, ch = c & 3;
        const __half* src = g_Wf + ((size_t)widx * NH + row) * NC + k0 + ch * 8;
        CPA16(sb + (uint32_t)st * STAGEB + PLANE4 + row * 80 + ch * 16, src);
    }
}

__global__ __launch_bounds__(256, 2)
void qkv_mma_kernel(const float* __restrict__ x) {
    extern __shared__ uint32_t smu[];
    const uint32_t sb = smem_u32(smu);

    const int bid  = (int)blockIdx.x;
    const int widx = bid % 3;                 // adjacent bids share the x tile
    const int m0   = (bid / 3) * 128;

    const int tid  = threadIdx.x;
    const int wid  = tid >> 5;
    const int lane = tid & 31;
    const int g    = lane >> 2;
    const int tig  = lane & 3;

    // A load mapping: 4 float4 per thread per chunk
    const int r0 = tid >> 3;                  // base row (+32 per it)
    const int c4 = (tid & 7) * 4;             // fp32 col within chunk
    const float* xb = x + (size_t)(m0 + r0) * NC + c4;
    const uint32_t aoff = (uint32_t)(r0 * 80 + c4 * 2);   // bytes into A plane

    // STS of 4 prefetched float4 -> fp16 into stage st's A plane
    auto stsA = [&](int st, const float4* v) {
        uint32_t base = sb + (uint32_t)st * STAGEB + aoff;
        #pragma unroll
        for (int it = 0; it < 4; it++) {
            uint2 p = make_uint2(pack_h2(v[it].x, v[it].y), pack_h2(v[it].z, v[it].w));
            asm volatile("st.shared.v2.u32 [%0], {%1, %2};"
                         :: "r"(base + it * (32 * 80)), "r"(p.x), "r"(p.y));
        }
    };
    auto ldA = [&](int c, float4* v) {
        const int k0 = c * 32;
        #pragma unroll
        for (int it = 0; it < 4; it++)
            v[it] = *(const float4*)(xb + (size_t)(32 * it) * NC + k0);
    };

    // prologue: A(0), A(1) direct to stages; regs <- A(2); B(0), B(1) cp.async
    {
        float4 v[4];
        ldA(0, v); stsA(0, v);
        ldA(1, v); stsA(1, v);
    }
    float4 pa[4];
    ldA(2, pa);
    qkv_load_B(sb, 0, widx, 0, tid);
    CP_COMMIT;
    qkv_load_B(sb, 1, widx, 32, tid);
    CP_COMMIT;

    float acc[2][8][4];
    #pragma unroll
    for (int mf = 0; mf < 2; mf++)
        #pragma unroll
        for (int nf = 0; nf < 8; nf++)
            #pragma unroll
            for (int i = 0; i < 4; i++) acc[mf][nf][i] = 0.f;

    const int mrow = (wid & 3) * 32 + g;
    const uint32_t offA = (uint32_t)(((wid & 3) * 32 + (lane & 7) + ((lane >> 3) & 1) * 8) * 80
                                     + ((lane >> 4) & 1) * 16);
    const uint32_t offB = (uint32_t)(((wid >> 2) * 64 + (lane & 7) + ((lane >> 4) & 1) * 8) * 80
                                     + ((lane >> 3) & 1) * 16);

    for (int c = 0; c < 32; c++) {
        const int st = c & 1;
        const uint32_t stage = sb + (uint32_t)st * STAGEB;

        CP_WAIT(1);          // B(c) complete
        __syncthreads();     // A STS visible

        #pragma unroll
        for (int ks = 0; ks < 2; ks++) {
            uint32_t af[2][4];
            #pragma unroll
            for (int mf = 0; mf < 2; mf++)
                ldm_x4(af[mf], stage + offA + mf * (16 * 80) + ks * 32);
            #pragma unroll
            for (int nfp = 0; nfp < 4; nfp++) {
                uint32_t b4[4];
                ldm_x4(b4, stage + PLANE4 + offB + nfp * (16 * 80) + ks * 32);
                #pragma unroll
                for (int mf = 0; mf < 2; mf++) {
                    mma_f16(acc[mf][2*nfp],   af[mf], b4);
                    mma_f16(acc[mf][2*nfp+1], af[mf], b4 + 2);
                }
            }
        }

        __syncthreads();     // all warps done reading stage st
        if (c + 2 < 32) {
            stsA(st, pa);                        // A(c+2) -> stage st
            qkv_load_B(sb, st, widx, (c + 2) * 32, tid);
        }
        CP_COMMIT;           // uniform group cadence
        if (c + 3 < 32) ldA(c + 3, pa);          // prefetch next A
    }

    // ---- epilogue: fp16 outputs ----
    if (widx < 2) {
        __half* of = (widx == 0) ? g_Qf : g_Kf;
        const float sc = (widx == 0) ? 0.08838834764831845f : 1.0f;
        #pragma unroll
        for (int mf = 0; mf < 2; mf++) {
            const int crow = m0 + mrow + mf * 16;
            #pragma unroll
            for (int nf = 0; nf < 8; nf++) {
                const int ccol = (wid >> 2) * 64 + nf * 8 + tig * 2;
                *(uint32_t*)&of[(size_t)crow * NH + ccol] =
                    pack_h2(acc[mf][nf][0]*sc, acc[mf][nf][1]*sc);
                *(uint32_t*)&of[(size_t)(crow + 8) * NH + ccol] =
                    pack_h2(acc[mf][nf][2]*sc, acc[mf][nf][3]*sc);
            }
        }
    } else {
        // V transpose to [d][t] via smem, then coalesced writes
        __half* sv = (__half*)smu;             // [128 d][136]
        __syncthreads();
        #pragma unroll
        for (int mf = 0; mf < 2; mf++) {
            const int rl = mrow + mf * 16;
            #pragma unroll
            for (int nf = 0; nf < 8; nf++) {
                const int ccol = (wid >> 2) * 64 + nf * 8 + tig * 2;
                #pragma unroll
                for (int e = 0; e < 4; e++) {
                    int d = ccol + (e & 1);
                    int m = rl + (e >> 1) * 8;
                    sv[d * 136 + m] = __float2half(acc[mf][nf][e]);
                }
            }
        }
        __syncthreads();
        const int b  = m0 >> 11;
        const int t0 = m0 & 2047;
        #pragma unroll
        for (int i = 0; i < 8; i++) {
            int c = tid + i * 256;          // 2048 chunks of 16B
            int d = c >> 4, col = c & 15;
            *(float4*)(g_Vtf + ((size_t)b * NH + d) * NT + t0 + col * 8) =
                *(const float4*)(sv + d * 136 + col * 8);
        }
    }
}

// ===========================================================================
// Flash attention, fp16. 64-key tiles, 2 CTAs/SM. Loads issued BEFORE softmax.
// smem: Q[0,17408) K st[17408+st*17408) V st[52224+st*18432), total 89088.
// ===========================================================================
#define ATTN_SMEM 89088
#define KOFF 17408u
#define VOFF 52224u

__device__ __forceinline__ void load_K_tile(uint32_t sb, int b, int kt, int st, int tid) {
    const __half* kf = g_Kf + ((size_t)b * NT + kt * 64) * NH;
    uint32_t base = sb + KOFF + (uint32_t)st * 17408u;
    #pragma unroll
    for (int i = 0; i < 8; i++) {
        int c = tid + i * 128;             // 1024: 64 rows x 16 chunks
        int row = c >> 4, col = c & 15;
        CPA16(base + row * 272 + col * 16, kf + row * NH + col * 8);
    }
}
__device__ __forceinline__ void load_V_tile(uint32_t sb, int b, int kt, int st, int tid) {
    const __half* vf = g_Vtf + (size_t)b * NH * NT + kt * 64;
    uint32_t base = sb + VOFF + (uint32_t)st * 18432u;
    #pragma unroll
    for (int i = 0; i < 8; i++) {
        int c = tid + i * 128;             // 1024: 128 rows x 8 chunks
        int row = c >> 3, ch = c & 7;
        CPA16(base + row * 144 + ch * 16, vf + (size_t)row * NT + ch * 8);
    }
}

__global__ __launch_bounds__(128, 2)
void attn_kernel(float* __restrict__ out) {
    extern __shared__ char smc[];
    const uint32_t sb = smem_u32(smc);

    // Exact-cover balanced mapping (each (qtile,b) once)
    const int bid = (int)blockIdx.x;
    int qtile, b;
    if (bid < 104)      { qtile = bid >> 3;                b = bid & 7; }
    else if (bid < 108) { qtile = 13;                      b = bid - 104; }
    else if (bid < 148) { qtile = 27 + ((bid - 108) >> 3); b = (bid - 108) & 7; }
    else if (bid < 252) { qtile = 26 - ((bid - 148) >> 3); b = (bid - 148) & 7; }
    else                { qtile = 13;                      b = bid - 252 + 4; }
    const int q0  = qtile * 64;
    const int NKT = qtile + 1;

    const int tid  = threadIdx.x;
    const int lane = tid & 31;
    const int band = tid >> 5;
    const int g    = lane >> 2;
    const int tig  = lane & 3;

    // prologue: group0 = Q + K0; group1 = V0 + K1
    {
        const __half* qf = g_Qf + ((size_t)b * NT + q0) * NH;
        #pragma unroll
        for (int i = 0; i < 8; i++) {
            int c = tid + i * 128;
            int row = c >> 4, col = c & 15;
            CPA16(sb + row * 272 + col * 16, qf + row * NH + col * 8);
        }
        load_K_tile(sb, b, 0, 0, tid);
    }
    CP_COMMIT;
    load_V_tile(sb, b, 0, 0, tid);
    if (NKT > 1) load_K_tile(sb, b, 1, 1, tid);
    CP_COMMIT;
    CP_WAIT(1);
    __syncthreads();

    float m0 = -INFINITY, m1 = -INFINITY, l0 = 0.f, l1 = 0.f;
    float oacc[16][4];
    #pragma unroll
    for (int n = 0; n < 16; n++)
        #pragma unroll
        for (int e = 0; e < 4; e++) oacc[n][e] = 0.f;

    const int r0a = q0 + band * 16 + g;

    const uint32_t offQ = (uint32_t)((band * 16 + (lane & 7) + ((lane >> 3) & 1) * 8) * 272
                                     + ((lane >> 4) & 1) * 16);
    const uint32_t offK = (uint32_t)(((lane & 7) + ((lane >> 4) & 1) * 8) * 272
                                     + ((lane >> 3) & 1) * 16);
    const uint32_t offV = (uint32_t)((lane & 7) * 144 + (lane >> 3) * 16);

    for (int kt = 0; kt < NKT; kt++) {
        const int st = kt & 1;
        const uint32_t Kb = sb + KOFF + (uint32_t)st * 17408u;
        const uint32_t Vb = sb + VOFF + (uint32_t)st * 18432u;

        // ---- S = Q K^T : warp tile 16 x 64, k = 128 ----
        float cf[8][4];
        #pragma unroll
        for (int nf = 0; nf < 8; nf++)
            #pragma unroll
            for (int e = 0; e < 4; e++) cf[nf][e] = 0.f;

        #pragma unroll
        for (int ks = 0; ks < 8; ks++) {
            uint32_t qf4[4];
            ldm_x4(qf4, sb + offQ + ks * 32);
            #pragma unroll
            for (int nfp = 0; nfp < 4; nfp++) {
                uint32_t k4[4];
                ldm_x4(k4, Kb + offK + nfp * (16 * 272) + ks * 32);
                mma_f16(cf[2*nfp],   qf4, k4);
                mma_f16(cf[2*nfp+1], qf4, k4 + 2);
            }
        }

        // ---- issue next loads NOW (overlap DMA with softmax) ----
        __syncthreads();     // all warps done: K st (S reads), V st^1 (prev PV)
        if (kt + 2 < NKT) load_K_tile(sb, b, kt + 2, st, tid);
        if (kt + 1 < NKT) load_V_tile(sb, b, kt + 1, st ^ 1, tid);
        CP_COMMIT;

        // ---- causal mask (diagonal tile only) ----
        if (kt == qtile) {
            const int k0 = kt * 64;
            #pragma unroll
            for (int nf = 0; nf < 8; nf++) {
                int cb = k0 + nf * 8 + 2 * tig;
                if (cb     > r0a)     cf[nf][0] = -INFINITY;
                if (cb + 1 > r0a)     cf[nf][1] = -INFINITY;
                if (cb     > r0a + 8) cf[nf][2] = -INFINITY;
                if (cb + 1 > r0a + 8) cf[nf][3] = -INFINITY;
            }
        }

        // ---- online softmax (registers + quad shuffles) ----
        float rx0 = -INFINITY, rx1 = -INFINITY;
        #pragma unroll
        for (int nf = 0; nf < 8; nf++) {
            rx0 = fmaxf(rx0, fmaxf(cf[nf][0], cf[nf][1]));
            rx1 = fmaxf(rx1, fmaxf(cf[nf][2], cf[nf][3]));
        }
        rx0 = fmaxf(rx0, __shfl_xor_sync(0xffffffffu, rx0, 1));
        rx0 = fmaxf(rx0, __shfl_xor_sync(0xffffffffu, rx0, 2));
        rx1 = fmaxf(rx1, __shfl_xor_sync(0xffffffffu, rx1, 1));
        rx1 = fmaxf(rx1, __shfl_xor_sync(0xffffffffu, rx1, 2));
        float mn0 = fmaxf(m0, rx0), mn1 = fmaxf(m1, rx1);
        float al0 = (m0 == -INFINITY) ? 0.f : __expf(m0 - mn0);
        float al1 = (m1 == -INFINITY) ? 0.f : __expf(m1 - mn1);
        float rs0 = 0.f, rs1 = 0.f;
        #pragma unroll
        for (int nf = 0; nf < 8; nf++) {
            cf[nf][0] = (cf[nf][0] == -INFINITY) ? 0.f : __expf(cf[nf][0] - mn0);
            cf[nf][1] = (cf[nf][1] == -INFINITY) ? 0.f : __expf(cf[nf][1] - mn0);
            cf[nf][2] = (cf[nf][2] == -INFINITY) ? 0.f : __expf(cf[nf][2] - mn1);
            cf[nf][3] = (cf[nf][3] == -INFINITY) ? 0.f : __expf(cf[nf][3] - mn1);
            rs0 += cf[nf][0] + cf[nf][1];
            rs1 += cf[nf][2] + cf[nf][3];
        }
        rs0 += __shfl_xor_sync(0xffffffffu, rs0, 1);
        rs0 += __shfl_xor_sync(0xffffffffu, rs0, 2);
        rs1 += __shfl_xor_sync(0xffffffffu, rs1, 1);
        rs1 += __shfl_xor_sync(0xffffffffu, rs1, 2);
        m0 = mn0; m1 = mn1;
        l0 = l0 * al0 + rs0;
        l1 = l1 * al1 + rs1;

        #pragma unroll
        for (int n = 0; n < 16; n++) {
            oacc[n][0] *= al0; oacc[n][1] *= al0;
            oacc[n][2] *= al1; oacc[n][3] *= al1;
        }

        // P -> fp16 A-fragments (c-frag layout == A-frag layout)
        uint32_t pa[4][4];
        #pragma unroll
        for (int kc = 0; kc < 4; kc++) {
            pa[kc][0] = pack_h2(cf[2*kc][0],   cf[2*kc][1]);
            pa[kc][1] = pack_h2(cf[2*kc][2],   cf[2*kc][3]);
            pa[kc][2] = pack_h2(cf[2*kc+1][0], cf[2*kc+1][1]);
            pa[kc][3] = pack_h2(cf[2*kc+1][2], cf[2*kc+1][3]);
        }

        CP_WAIT(1);          // V(kt) (+K(kt+1)) ready
        __syncthreads();

        // ---- O += P V : 16 n-frags, k = 64 ----
        #pragma unroll
        for (int n = 0; n < 16; n++) {
            uint32_t va = Vb + offV + n * (8 * 144);
            uint32_t v4a[4], v4b[4];
            ldm_x4(v4a, va);          // t 0..31
            ldm_x4(v4b, va + 64);     // t 32..63
            mma_f16(oacc[n], pa[0], v4a);
            mma_f16(oacc[n], pa[1], v4a + 2);
            mma_f16(oacc[n], pa[2], v4b);
            mma_f16(oacc[n], pa[3], v4b + 2);
        }
    }

    const float il0 = 1.f / l0, il1 = 1.f / l1;
    float* Og  = out + ((size_t)b * NT + q0 + band * 16 + g) * NH;
    float* Og8 = Og + 8 * NH;
    #pragma unroll
    for (int n = 0; n < 16; n++) {
        const int cc = n * 8 + 2 * tig;
        *(float2*)&Og[cc]  = make_float2(oacc[n][0] * il0, oacc[n][1] * il0);
        *(float2*)&Og8[cc] = make_float2(oacc[n][2] * il1, oacc[n][3] * il1);
    }
}

// ---------------------------------------------------------------------------
extern "C" void kernel_launch(void* const* d_in, const int* in_sizes, int n_in,
                              void* d_out, int out_size) {
    const float* x  = (const float*)d_in[0];
    const float* Wq = (const float*)d_in[1];
    const float* Wk = (const float*)d_in[2];
    const float* Wv = (const float*)d_in[3];
    float* out = (float*)d_out;

    split_w<<<3 * WBLK, 256>>>(Wq, Wk, Wv);

    cudaFuncSetAttribute(qkv_mma_kernel,
                         cudaFuncAttributeMaxDynamicSharedMemorySize, QKV_SMEM);
    qkv_mma_kernel<<<3 * (NBT / 128), 256, QKV_SMEM>>>(x);

    cudaFuncSetAttribute(attn_kernel,
                         cudaFuncAttributeMaxDynamicSharedMemorySize, ATTN_SMEM);
    attn_kernel<<<256, 128, ATTN_SMEM>>>(out);
}